// round 6
// baseline (speedup 1.0000x reference)
#include <cuda_runtime.h>
#include <cstdint>

// CompressK: mean-pool over sliding windows of 32 rows, stride 16.
// k: (BATCH*SEQ_LEN, 4, 128) fp32 -> row = 512 floats = 128 float4
// out: (4092, 4, 128) fp32 followed by cu_comp (BATCH+1) as fp32 values.
//
// Block-sum sharing: chunk c = (S_c + S_{c+1}) / 32, S_j = sum of 16-row
// block j. CH=16 chunks/segment -> 17 block-sums -> 1.0625x minimal read.
// Column-split: each block covers a quarter-row (32 float4) so CH=16 still
// yields grid=1024 (27.7 warps/SM, the proven BW-sufficient point).

#define BATCH 4
#define SEQ_LEN 16384
#define ROW_FLOATS 512
#define ROW_F4 128
#define CHUNKS_PER_BATCH 1023     // (16384-32)/16 + 1
#define TOTAL_CHUNKS (BATCH * CHUNKS_PER_BATCH)   // 4092
#define CH 16
#define SEGS_PER_BATCH ((CHUNKS_PER_BATCH + CH - 1) / CH)    // 64
#define COL_SPLIT 4
#define COLQ_F4 (ROW_F4 / COL_SPLIT)              // 32 float4 per block
#define COLQ_FLOATS (COLQ_F4 * 4)                 // 128 floats per block
#define OUT_FLOATS ((size_t)TOTAL_CHUNKS * ROW_FLOATS)       // 2,095,104
#define NTHREADS 128

__global__ __launch_bounds__(NTHREADS) void compress_k_kernel(
    const float4* __restrict__ k4, float* __restrict__ out)
{
    __shared__ float4 part[2][4][COLQ_F4];   // [buf][row-quarter][f4 col]

    const int tid  = threadIdx.x;            // 0..127
    const int col4 = tid & (COLQ_F4 - 1);    // f4 column within quarter
    const int q    = tid >> 5;               // row quarter 0..3

    // grid: bx = ((batch * SEGS_PER_BATCH) + seg) * COL_SPLIT + colq
    const int colq  = blockIdx.x & (COL_SPLIT - 1);
    const int rest  = blockIdx.x >> 2;
    const int seg   = rest & (SEGS_PER_BATCH - 1);
    const int batch = rest >> 6;

    // Fused cu_comp tail (fp32 values; exact for these magnitudes)
    if (blockIdx.x == 0 && tid <= BATCH) {
        out[OUT_FLOATS + tid] = (float)(tid * CHUNKS_PER_BATCH);
    }

    const int c_begin = seg * CH;
    int nch = CHUNKS_PER_BATCH - c_begin;
    if (nch > CH) nch = CH;

    const size_t base_row = (size_t)batch * SEQ_LEN + (size_t)c_begin * 16;
    // this thread's first row within each 16-row block-sum: q*4
    const float4* src = k4 + (base_row + (size_t)q * 4) * ROW_F4
                           + (size_t)colq * COLQ_F4 + col4;

    const float* partf = (const float*)part;   // scalar view

    const float inv32 = 1.0f / 32.0f;
    float sPrev = 0.0f;
    int buf = 0;

    const size_t out_base = ((size_t)batch * CHUNKS_PER_BATCH + c_begin) * ROW_FLOATS
                          + (size_t)colq * COLQ_FLOATS + tid;

    for (int j = 0; j <= nch; ++j) {
        // 4 independent LDG.128 (rows j*16 + q*4 + 0..3)
        const float4* p = src + (size_t)j * 16 * ROW_F4;
        float4 v0 = p[0 * ROW_F4];
        float4 v1 = p[1 * ROW_F4];
        float4 v2 = p[2 * ROW_F4];
        float4 v3 = p[3 * ROW_F4];
        float4 ps;
        ps.x = (v0.x + v1.x) + (v2.x + v3.x);
        ps.y = (v0.y + v1.y) + (v2.y + v3.y);
        ps.z = (v0.z + v1.z) + (v2.z + v3.z);
        ps.w = (v0.w + v1.w) + (v2.w + v3.w);
        part[buf][q][col4] = ps;

        __syncthreads();

        // combine: thread owns scalar float column tid (within quarter)
        const float* pb = partf + (size_t)buf * 4 * COLQ_FLOATS;
        float s = (pb[0 * COLQ_FLOATS + tid] + pb[1 * COLQ_FLOATS + tid])
                + (pb[2 * COLQ_FLOATS + tid] + pb[3 * COLQ_FLOATS + tid]);

        if (j > 0) {
            out[out_base + (size_t)(j - 1) * ROW_FLOATS] = (sPrev + s) * inv32;
        }
        sPrev = s;
        buf ^= 1;
    }
}

extern "C" void kernel_launch(void* const* d_in, const int* in_sizes, int n_in,
                              void* d_out, int out_size)
{
    const float4* k4 = (const float4*)d_in[0];

    dim3 grid(BATCH * SEGS_PER_BATCH * COL_SPLIT);   // 1024
    compress_k_kernel<<<grid, NTHREADS>>>(k4, (float*)d_out);
}